// round 2
// baseline (speedup 1.0000x reference)
#include <cuda_runtime.h>
#include <cuda_bf16.h>

#define TT    111
#define NCTA  128
#define SMEM_FLOATS 51824
#define SMEM_BYTES  (SMEM_FLOATS * 4)

// ---- float32x2 packed helpers (Blackwell dual-FP32 path) ----
__device__ __forceinline__ unsigned long long pk2(float a, float b) {
    unsigned long long r;
    asm("mov.b64 %0, {%1,%2};" : "=l"(r) : "f"(a), "f"(b));
    return r;
}
__device__ __forceinline__ void upk2(unsigned long long v, float &a, float &b) {
    asm("mov.b64 {%0,%1}, %2;" : "=f"(a), "=f"(b) : "l"(v));
}
__device__ __forceinline__ unsigned long long ffma2(unsigned long long a,
                                                    unsigned long long b,
                                                    unsigned long long c) {
    unsigned long long d;
    asm("fma.rn.f32x2 %0, %1, %2, %3;" : "=l"(d) : "l"(a), "l"(b), "l"(c));
    return d;
}
// accurate-enough fast sigmoid/tanh: EX2+RCP based, rel err ~1e-6
__device__ __forceinline__ float fsig(float x) {
    float e = __expf(-x);
    return __fdividef(1.f, 1.f + e);
}
__device__ __forceinline__ float ftanhx(float x) {
    x = fminf(15.f, fmaxf(-15.f, x));
    float e = __expf(-2.f * x);
    return __fdividef(1.f - e, 1.f + e);
}

// Shared memory layout (float offsets):
//   Wsm   [4][64][128]  @ 0       (k-major, gate-interleaved: gate' = unit*4+gt)
//   Bsm   [4][128]      @ 32768   (bih+bhh, interleaved)
//   WaS   [32]          @ 33280
//   B1S   [32]          @ 33312
//   W1S   [32][32]      @ 33344
//   W2S   [32][3]       @ 34368
//   MS    [4]           @ 34464   (ba, b2[0..2])  (+pad to 16B)
//   A2    [8][5][4][32] float2 @ 34480  (per-warp: slot0=x, slot1..4=h of layer0..3)
//   XI    [64][111] int @ 44720
extern "C" __global__ void __launch_bounds__(256, 1)
lstm_fused_kernel(const int* __restrict__ x, const float* __restrict__ emb,
                  const float* __restrict__ Wih, const float* __restrict__ Whh,
                  const float* __restrict__ bih, const float* __restrict__ bhh,
                  const float* __restrict__ Wa, const float* __restrict__ ba,
                  const float* __restrict__ W1, const float* __restrict__ b1,
                  const float* __restrict__ W2, const float* __restrict__ b2,
                  float* __restrict__ out)
{
    extern __shared__ float sm[];
    float*  Wsm = sm;
    float*  Bsm = sm + 32768;
    float*  WaS = sm + 33280;
    float*  B1S = sm + 33312;
    float*  W1S = sm + 33344;
    float*  W2S = sm + 34368;
    float*  MS  = sm + 34464;
    float2* A2  = (float2*)(sm + 34480);
    int*    XI  = (int*)(sm + 44720);

    const int tid  = threadIdx.x;
    const int w    = tid >> 5;
    const int lane = tid & 31;
    const int cta  = blockIdx.x;

    // ---- stage weights (remap to k-major + gate-interleaved) ----
    for (int i = tid; i < 4 * 64 * 128; i += 256) {
        int gp = i & 127, k = (i >> 7) & 63, l = i >> 13;
        int u = gp >> 2, gt = gp & 3;
        int row = gt * 32 + u;
        float wv = (k < 32) ? Wih[(l * 128 + row) * 32 + k]
                            : Whh[(l * 128 + row) * 32 + (k - 32)];
        Wsm[i] = wv;
    }
    for (int i = tid; i < 512; i += 256) {
        int gp = i & 127, l = i >> 7;
        int row = (gp & 3) * 32 + (gp >> 2);
        Bsm[i] = bih[l * 128 + row] + bhh[l * 128 + row];
    }
    if (tid < 32) { WaS[tid] = Wa[tid]; B1S[tid] = b1[tid]; }
    for (int i = tid; i < 1024; i += 256) W1S[i] = W1[i];
    if (tid < 96) W2S[tid] = W2[tid];
    if (tid == 0) { MS[0] = ba[0]; MS[1] = b2[0]; MS[2] = b2[1]; MS[3] = b2[2]; }
    for (int i = tid; i < 64 * 111; i += 256) XI[i] = x[cta * 64 * 111 + i];
    for (int i = tid; i < 8 * 5 * 4 * 32; i += 256) A2[i] = make_float2(0.f, 0.f);
    __syncthreads();
    // ---- from here on, warps are fully independent (each owns 8 rows) ----

    float2* A2w = A2 + w * 640;   // [5][4][32]

    float cst[32];                 // c-state: [layer][row 0..7]
#pragma unroll
    for (int i = 0; i < 32; i++) cst[i] = 0.f;
    float ctx[8], se[8];
#pragma unroll
    for (int r = 0; r < 8; r++) { ctx[r] = 0.f; se[r] = 0.f; }
    const float waL = WaS[lane];
    const float baS = MS[0];

    // preload embedding for t=0 into slot0 (packed row pairs)
#pragma unroll
    for (int rp = 0; rp < 4; ++rp) {
        int xi0 = XI[(w * 8 + rp * 2) * TT];
        int xi1 = XI[(w * 8 + rp * 2 + 1) * TT];
        float e0 = emb[xi0 * 32 + lane];
        float e1 = emb[xi1 * 32 + lane];
        A2w[rp * 32 + lane] = make_float2(e0, e1);
    }
    __syncwarp();

    float pv0[8];

    for (int t = 0; t < TT; ++t) {
        float h3[8];
#pragma unroll
        for (int l = 0; l < 4; ++l) {
            unsigned long long acc[16];   // [gt][rp]
            float4 bg = *(const float4*)(Bsm + l * 128 + 4 * lane);
#pragma unroll
            for (int rp = 0; rp < 4; ++rp) {
                acc[0 * 4 + rp] = pk2(bg.x, bg.x);
                acc[1 * 4 + rp] = pk2(bg.y, bg.y);
                acc[2 * 4 + rp] = pk2(bg.z, bg.z);
                acc[3 * 4 + rp] = pk2(bg.w, bg.w);
            }
#pragma unroll
            for (int part = 0; part < 2; ++part) {
                const float2* inp = A2w + (part == 0 ? l : (l + 1)) * 128;
                const float*  wp  = Wsm + (l * 64 + part * 32) * 128 + 4 * lane;
#pragma unroll 2
                for (int k = 0; k < 32; k += 2) {
                    float4 w0 = *(const float4*)(wp + k * 128);
                    float4 w1 = *(const float4*)(wp + (k + 1) * 128);
                    unsigned long long wa0 = pk2(w0.x, w0.x), wb0 = pk2(w0.y, w0.y);
                    unsigned long long wc0 = pk2(w0.z, w0.z), wd0 = pk2(w0.w, w0.w);
                    unsigned long long wa1 = pk2(w1.x, w1.x), wb1 = pk2(w1.y, w1.y);
                    unsigned long long wc1 = pk2(w1.z, w1.z), wd1 = pk2(w1.w, w1.w);
#pragma unroll
                    for (int rp = 0; rp < 4; ++rp) {
                        ulonglong2 iv = *(const ulonglong2*)(inp + rp * 32 + k);
                        acc[0 * 4 + rp] = ffma2(wa0, iv.x, acc[0 * 4 + rp]);
                        acc[1 * 4 + rp] = ffma2(wb0, iv.x, acc[1 * 4 + rp]);
                        acc[2 * 4 + rp] = ffma2(wc0, iv.x, acc[2 * 4 + rp]);
                        acc[3 * 4 + rp] = ffma2(wd0, iv.x, acc[3 * 4 + rp]);
                        acc[0 * 4 + rp] = ffma2(wa1, iv.y, acc[0 * 4 + rp]);
                        acc[1 * 4 + rp] = ffma2(wb1, iv.y, acc[1 * 4 + rp]);
                        acc[2 * 4 + rp] = ffma2(wc1, iv.y, acc[2 * 4 + rp]);
                        acc[3 * 4 + rp] = ffma2(wd1, iv.y, acc[3 * 4 + rp]);
                    }
                }
            }
            // gates -> cell update -> h (PyTorch gate order i,f,g,o)
#pragma unroll
            for (int rp = 0; rp < 4; ++rp) {
                float i0, i1, f0, f1, g0, g1, o0, o1;
                upk2(acc[0 * 4 + rp], i0, i1);
                upk2(acc[1 * 4 + rp], f0, f1);
                upk2(acc[2 * 4 + rp], g0, g1);
                upk2(acc[3 * 4 + rp], o0, o1);
                float c0 = cst[l * 8 + rp * 2], c1 = cst[l * 8 + rp * 2 + 1];
                c0 = fsig(f0) * c0 + fsig(i0) * ftanhx(g0);
                c1 = fsig(f1) * c1 + fsig(i1) * ftanhx(g1);
                float h0 = fsig(o0) * ftanhx(c0);
                float h1 = fsig(o1) * ftanhx(c1);
                cst[l * 8 + rp * 2] = c0;
                cst[l * 8 + rp * 2 + 1] = c1;
                A2w[(l + 1) * 128 + rp * 32 + lane] = make_float2(h0, h1);
                if (l == 3) { h3[rp * 2] = h0; h3[rp * 2 + 1] = h1; }
            }
            __syncwarp();
            if (l == 0 && t + 1 < TT) {
                // prefetch next step's embedding; latency hides under layers 1..3
#pragma unroll
                for (int rr = 0; rr < 8; ++rr) {
                    int xi = XI[(w * 8 + rr) * TT + (t + 1)];
                    pv0[rr] = emb[xi * 32 + lane];
                }
            }
        }
        // streaming attention (scores are tiny: no max-subtraction needed)
#pragma unroll
        for (int r = 0; r < 8; ++r) {
            float p = h3[r] * waL;
            p += __shfl_xor_sync(0xffffffffu, p, 16);
            p += __shfl_xor_sync(0xffffffffu, p, 8);
            p += __shfl_xor_sync(0xffffffffu, p, 4);
            p += __shfl_xor_sync(0xffffffffu, p, 2);
            p += __shfl_xor_sync(0xffffffffu, p, 1);
            float e = __expf(p + baS);
            se[r] += e;
            ctx[r] = fmaf(e, h3[r], ctx[r]);
        }
        if (t + 1 < TT) {
#pragma unroll
            for (int rp = 0; rp < 4; ++rp)
                A2w[rp * 32 + lane] = make_float2(pv0[rp * 2], pv0[rp * 2 + 1]);
            __syncwarp();
        }
    }

    // ---- head: context -> tanh(ctx@W1+b1) -> @W2+b2 (per-warp, via scratch) ----
    float* scr = (float*)A2w;     // 1280 floats/warp: [0..255]=ctx, [256..511]=hid
#pragma unroll
    for (int r = 0; r < 8; ++r) scr[r * 32 + lane] = __fdividef(ctx[r], se[r]);
    __syncwarp();
    float hidv[8];
#pragma unroll
    for (int r = 0; r < 8; ++r) {
        float a = B1S[lane];
#pragma unroll
        for (int u = 0; u < 32; ++u) a = fmaf(scr[r * 32 + u], W1S[u * 32 + lane], a);
        hidv[r] = ftanhx(a);
    }
    __syncwarp();
#pragma unroll
    for (int r = 0; r < 8; ++r) scr[256 + r * 32 + lane] = hidv[r];
    __syncwarp();
    int rr = lane >> 2, kq = lane & 3;
    if (kq < 3) {
        float a = MS[1 + kq];
#pragma unroll
        for (int j = 0; j < 32; ++j) a = fmaf(scr[256 + rr * 32 + j], W2S[j * 3 + kq], a);
        out[(cta * 64 + w * 8 + rr) * 3 + kq] = a;
    }
}

extern "C" void kernel_launch(void* const* d_in, const int* in_sizes, int n_in,
                              void* d_out, int out_size) {
    (void)in_sizes; (void)n_in; (void)out_size;
    const int*   x   = (const int*)d_in[0];
    const float* emb = (const float*)d_in[1];
    const float* Wih = (const float*)d_in[2];
    const float* Whh = (const float*)d_in[3];
    const float* bih = (const float*)d_in[4];
    const float* bhh = (const float*)d_in[5];
    const float* Wa  = (const float*)d_in[6];
    const float* ba  = (const float*)d_in[7];
    const float* W1  = (const float*)d_in[8];
    const float* b1  = (const float*)d_in[9];
    const float* W2  = (const float*)d_in[10];
    const float* b2  = (const float*)d_in[11];
    float* out = (float*)d_out;

    cudaFuncSetAttribute(lstm_fused_kernel,
                         cudaFuncAttributeMaxDynamicSharedMemorySize, SMEM_BYTES);
    lstm_fused_kernel<<<NCTA, 256, SMEM_BYTES>>>(x, emb, Wih, Whh, bih, bhh,
                                                 Wa, ba, W1, b1, W2, b2, out);
}

// round 3
// speedup vs baseline: 1.0612x; 1.0612x over previous
#include <cuda_runtime.h>
#include <cuda_bf16.h>

#define TT    111
#define NCTA  128

// ---- shared memory layout (float offsets) ----
// W4   [4][16][128] float4 @ 0        (k-minor: float4 = w[gp][4kb..4kb+3])  131072 B
// Bsm  [4][128]            @ 32768    (bih+bhh, native gate-major)
// WaS  [32]                @ 33280
// B1S  [32]                @ 33312
// W1S  [32][32]            @ 33344
// W2S  [32][3]             @ 34368
// MS   [4]                 @ 34464    (ba, b2[0..2])
// A    [8 warps][8 rows][160] @ 34496 (slot s at col s*32; slot0=x, slot1..4=h l0..l3)
// Csm  [8 warps][4][8][32] @ 44736
#define SMEM_FLOATS 52928
#define SMEM_BYTES  (SMEM_FLOATS * 4)

typedef unsigned long long u64;

__device__ __forceinline__ u64 pk0() {
    u64 r; asm("mov.b64 %0, {%1,%1};" : "=l"(r) : "f"(0.f)); return r;
}
__device__ __forceinline__ u64 ffma2(u64 a, u64 b, u64 c) {
    u64 d; asm("fma.rn.f32x2 %0, %1, %2, %3;" : "=l"(d) : "l"(a), "l"(b), "l"(c));
    return d;
}
__device__ __forceinline__ float red2(u64 v) {
    float a, b; asm("mov.b64 {%0,%1}, %2;" : "=f"(a), "=f"(b) : "l"(v));
    return a + b;
}
// sigmoid: 1/(1+e^-x), exp via __expf (EX2, ~2ulp). tanh = 2*sig(2x)-1 (overflow-graceful).
__device__ __forceinline__ float fsig(float x) {
    return __fdividef(1.f, 1.f + __expf(-x));
}
__device__ __forceinline__ float ftanh(float x) {
    float s = __fdividef(1.f, 1.f + __expf(-2.f * x));
    return fmaf(2.f, s, -1.f);
}

extern "C" __global__ void __launch_bounds__(256, 1)
lstm_fused_kernel(const int* __restrict__ x, const float* __restrict__ emb,
                  const float* __restrict__ Wih, const float* __restrict__ Whh,
                  const float* __restrict__ bih, const float* __restrict__ bhh,
                  const float* __restrict__ Wa, const float* __restrict__ ba,
                  const float* __restrict__ W1, const float* __restrict__ b1,
                  const float* __restrict__ W2, const float* __restrict__ b2,
                  float* __restrict__ out)
{
    extern __shared__ float sm[];
    float4* W4  = (float4*)sm;
    float*  Bsm = sm + 32768;
    float*  WaS = sm + 33280;
    float*  B1S = sm + 33312;
    float*  W1S = sm + 33344;
    float*  W2S = sm + 34368;
    float*  MS  = sm + 34464;
    float*  A0  = sm + 34496;
    float*  C0  = sm + 44736;

    const int tid  = threadIdx.x;
    const int w    = tid >> 5;
    const int lane = tid & 31;
    const int cta  = blockIdx.x;

    // ---- stage weights: W4[(l*16+kb)*128 + gp] = float4 of w[gp][4kb..4kb+3] ----
    for (int d = tid; d < 8192; d += 256) {
        int gp = d & 127, kb = (d >> 7) & 15, l = d >> 11;
        float4 v;
        if (kb < 8) v = *(const float4*)(Wih + (l * 128 + gp) * 32 + kb * 4);
        else        v = *(const float4*)(Whh + (l * 128 + gp) * 32 + (kb - 8) * 4);
        W4[d] = v;
    }
    for (int i = tid; i < 512; i += 256)
        Bsm[i] = bih[i] + bhh[i];
    if (tid < 32) { WaS[tid] = Wa[tid]; B1S[tid] = b1[tid]; }
    for (int i = tid; i < 1024; i += 256) W1S[i] = W1[i];
    if (tid < 96) W2S[tid] = W2[tid];
    if (tid == 0) { MS[0] = ba[0]; MS[1] = b2[0]; MS[2] = b2[1]; MS[3] = b2[2]; }
    for (int i = tid; i < 8 * 1280; i += 256) A0[i] = 0.f;
    for (int i = tid; i < 8 * 1024; i += 256) C0[i] = 0.f;
    __syncthreads();
    // ---- warps fully independent from here (each owns 8 batch rows) ----

    float* Aw = A0 + w * 1280;   // [8 rows][160]
    float* Cw = C0 + w * 1024;   // [4 l][8 rows][32]

    const float waL = WaS[lane];
    const float baS = MS[0];
    float ctx[8], se[8];
#pragma unroll
    for (int r = 0; r < 8; ++r) { ctx[r] = 0.f; se[r] = 0.f; }

    // x-index prefetch: lanes 0..7 hold the indices of their row
    const int xrow = cta * 64 + w * 8 + (lane & 7);
    int xi0 = 0, xnext = 0, xfut = 0;
    if (lane < 8) { xi0 = x[xrow * TT]; xnext = x[xrow * TT + 1]; }
    // emb for t=0 into slot0
#pragma unroll
    for (int rr = 0; rr < 8; ++rr) {
        int xv = __shfl_sync(0xffffffffu, xi0, rr);
        Aw[rr * 160 + lane] = emb[xv * 32 + lane];
    }
    __syncwarp();

    float pv0[8];

    for (int t = 0; t < TT; ++t) {
        for (int l = 0; l < 4; ++l) {
            const float4* wpl = W4 + l * 2048 + lane;   // + kb*128 + g*32
            const float*  rb  = Aw + l * 32;            // + r*160 + kb*4
            u64 acc[32];
            u64 z0 = pk0();
#pragma unroll
            for (int i = 0; i < 32; ++i) acc[i] = z0;

#pragma unroll
            for (int kb = 0; kb < 16; ++kb) {
                ulonglong2 wq[4];
#pragma unroll
                for (int g = 0; g < 4; ++g)
                    wq[g] = *(const ulonglong2*)(wpl + kb * 128 + g * 32);
                ulonglong2 xq[8];
#pragma unroll
                for (int r = 0; r < 8; ++r)
                    xq[r] = *(const ulonglong2*)(rb + r * 160 + kb * 4);
#pragma unroll
                for (int r = 0; r < 8; ++r)
#pragma unroll
                    for (int g = 0; g < 4; ++g)
                        acc[g * 8 + r] = ffma2(wq[g].x, xq[r].x, acc[g * 8 + r]);
#pragma unroll
                for (int r = 0; r < 8; ++r)
#pragma unroll
                    for (int g = 0; g < 4; ++g)
                        acc[g * 8 + r] = ffma2(wq[g].y, xq[r].y, acc[g * 8 + r]);
            }

            const float bi = Bsm[l * 128 + lane];
            const float bf = Bsm[l * 128 + 32 + lane];
            const float bg = Bsm[l * 128 + 64 + lane];
            const float bo = Bsm[l * 128 + 96 + lane];
#pragma unroll
            for (int r = 0; r < 8; ++r) {
                float zi = red2(acc[0 * 8 + r]) + bi;
                float zf = red2(acc[1 * 8 + r]) + bf;
                float zg = red2(acc[2 * 8 + r]) + bg;
                float zo = red2(acc[3 * 8 + r]) + bo;
                float c  = Cw[l * 256 + r * 32 + lane];
                c = fsig(zf) * c + fsig(zi) * ftanh(zg);
                float h = fsig(zo) * ftanh(c);
                Cw[l * 256 + r * 32 + lane] = c;
                Aw[r * 160 + (l + 1) * 32 + lane] = h;
            }
            __syncwarp();

            if (l == 0 && t + 1 < TT) {
                // prefetch next step's embedding (hidden under layers 1..3)
#pragma unroll
                for (int rr = 0; rr < 8; ++rr) {
                    int xv = __shfl_sync(0xffffffffu, xnext, rr);
                    pv0[rr] = emb[xv * 32 + lane];
                }
                xfut = 0;
                if (lane < 8 && t + 2 < TT) xfut = x[xrow * TT + t + 2];
            }
        }

        // streaming attention over slot4 h (scores tiny: no max-subtract)
#pragma unroll
        for (int r = 0; r < 8; ++r) {
            float h3 = Aw[r * 160 + 128 + lane];
            float p = h3 * waL;
            p += __shfl_xor_sync(0xffffffffu, p, 16);
            p += __shfl_xor_sync(0xffffffffu, p, 8);
            p += __shfl_xor_sync(0xffffffffu, p, 4);
            p += __shfl_xor_sync(0xffffffffu, p, 2);
            p += __shfl_xor_sync(0xffffffffu, p, 1);
            float e = __expf(p + baS);
            se[r] += e;
            ctx[r] = fmaf(e, h3, ctx[r]);
        }
        if (t + 1 < TT) {
#pragma unroll
            for (int rr = 0; rr < 8; ++rr) Aw[rr * 160 + lane] = pv0[rr];
            xnext = xfut;
            __syncwarp();
        }
    }

    // ---- head (per warp, scratch reuses Aw: 512 floats needed, 1280 avail) ----
    float* scr = Aw;
#pragma unroll
    for (int r = 0; r < 8; ++r) scr[r * 32 + lane] = __fdividef(ctx[r], se[r]);
    __syncwarp();
    float hidv[8];
#pragma unroll
    for (int r = 0; r < 8; ++r) {
        float a = B1S[lane];
#pragma unroll
        for (int u = 0; u < 32; ++u) a = fmaf(scr[r * 32 + u], W1S[u * 32 + lane], a);
        hidv[r] = ftanh(a);
    }
    __syncwarp();
#pragma unroll
    for (int r = 0; r < 8; ++r) scr[256 + r * 32 + lane] = hidv[r];
    __syncwarp();
    int rr = lane >> 2, kq = lane & 3;
    if (kq < 3) {
        float a = MS[1 + kq];
#pragma unroll
        for (int j = 0; j < 32; ++j) a = fmaf(scr[256 + rr * 32 + j], W2S[j * 3 + kq], a);
        out[(cta * 64 + w * 8 + rr) * 3 + kq] = a;
    }
}

extern "C" void kernel_launch(void* const* d_in, const int* in_sizes, int n_in,
                              void* d_out, int out_size) {
    (void)in_sizes; (void)n_in; (void)out_size;
    const int*   x   = (const int*)d_in[0];
    const float* emb = (const float*)d_in[1];
    const float* Wih = (const float*)d_in[2];
    const float* Whh = (const float*)d_in[3];
    const float* bih = (const float*)d_in[4];
    const float* bhh = (const float*)d_in[5];
    const float* Wa  = (const float*)d_in[6];
    const float* ba  = (const float*)d_in[7];
    const float* W1  = (const float*)d_in[8];
    const float* b1  = (const float*)d_in[9];
    const float* W2  = (const float*)d_in[10];
    const float* b2  = (const float*)d_in[11];
    float* out = (float*)d_out;

    cudaFuncSetAttribute(lstm_fused_kernel,
                         cudaFuncAttributeMaxDynamicSharedMemorySize, SMEM_BYTES);
    lstm_fused_kernel<<<NCTA, 256, SMEM_BYTES>>>(x, emb, Wih, Whh, bih, bhh,
                                                 Wa, ba, W1, b1, W2, b2, out);
}